// round 7
// baseline (speedup 1.0000x reference)
#include <cuda_runtime.h>

#define BB 64
#define NN 512
#define EPS 1e-10f

// Scratch (allocation-free rule: __device__ globals; zero-init at load,
// reset by the finalize block each run for graph replay)
__device__ float4   g_items[BB * NN];   // rel-sorted: {gain, disc, exp(s), lo_as_int}
__device__ float    g_rowScale[BB];     // ln2 / (idcg * (cnt+eps)) / B
__device__ unsigned g_slot[BB * 5];     // within-bucket placement counters
__device__ float    g_accum = 0.0f;
__device__ unsigned g_count = 0u;

// ---------------- Kernel 1: ranks + sorted placement + row constants -----------
// grid (16, 64), 256 threads. Block q owns items [q*32, q*32+32).
// 8 threads/item scan 64 scores each (LDS.32, 8 adjacent addrs/warp = broadcast).
// Tie-break (j < i) via loop split; bucket slot via global atomic.
__global__ __launch_bounds__(256, 8)
void lr_prep(const float* __restrict__ scores,
             const float* __restrict__ relevance) {
    const int q   = blockIdx.x;      // 0..15
    const int row = blockIdx.y;
    const int t   = threadIdx.x;

    __shared__ float ss[NN];
    __shared__ int   counts[5];
    __shared__ float wred[8];

    if (t < 5) counts[t] = 0;
    ss[t]       = scores[row * NN + t];
    ss[t + 256] = scores[row * NN + t + 256];
    float r0 = relevance[row * NN + t];
    float r1 = relevance[row * NN + t + 256];
    __syncthreads();
    atomicAdd(&counts[(int)r0], 1);
    atomicAdd(&counts[(int)r1], 1);

    const int   i    = q * 32 + (t >> 3);
    const int   part = t & 7;
    const float si   = ss[i];
    const int   thr  = (i - part + 7) >> 3;    // #jj with 8jj+part < i

    int rk = 0, jj = 0;
    #pragma unroll 8
    for (; jj < thr; ++jj) rk += (ss[8 * jj + part] >= si);   // j < i
    #pragma unroll 8
    for (; jj < 64; ++jj)  rk += (ss[8 * jj + part] > si);    // j >= i
    rk += __shfl_down_sync(0xffffffffu, rk, 4, 8);
    rk += __shfl_down_sync(0xffffffffu, rk, 2, 8);
    rk += __shfl_down_sync(0xffffffffu, rk, 1, 8);

    __syncthreads();                           // histogram complete
    const int c4 = counts[4], c3 = counts[3], c2 = counts[2], c1 = counts[1];

    if (part == 0) {
        int ri = (int)relevance[row * NN + i];
        int base = (ri == 4) ? 0
                 : (ri == 3) ? c4
                 : (ri == 2) ? c4 + c3
                 : (ri == 1) ? c4 + c3 + c2
                             : c4 + c3 + c2 + c1;
        int cr = (ri == 4) ? c4 : (ri == 3) ? c3 : (ri == 2) ? c2
               : (ri == 1) ? c1 : (NN - (c4 + c3 + c2 + c1));
        unsigned slot = atomicAdd(&g_slot[row * 5 + ri], 1u);
        float g = (float)((1 << ri) - 1);
        float d = __fdividef(1.0f, __log2f((float)(rk + 3)));  // rank = rk+1
        g_items[row * NN + base + (int)slot] =
            make_float4(g, d, __expf(si), __int_as_float(base + cr));
    }

    // Row constants (q==0 only; block-uniform branch)
    if (q == 0) {
        int b4 = c4, b3 = b4 + c3, b2 = b3 + c2, b1 = b2 + c1;
        float v = 0.0f;
        #pragma unroll
        for (int h = 0; h < 2; ++h) {
            int p = t + h * 256;
            float gl = p < b4 ? 15.f : p < b3 ? 7.f : p < b2 ? 3.f : p < b1 ? 1.f : 0.f;
            v += __fdividef(gl, __log2f((float)(p + 2)));
        }
        #pragma unroll
        for (int o = 16; o > 0; o >>= 1) v += __shfl_down_sync(0xffffffffu, v, o);
        if ((t & 31) == 0) wred[t >> 5] = v;
        __syncthreads();
        if (t == 0) {
            float idcg = fmaxf(wred[0] + wred[1] + wred[2] + wred[3] +
                               wred[4] + wred[5] + wred[6] + wred[7], EPS);
            int c0 = NN - (c4 + c3 + c2 + c1);
            float sq = (float)c4 * c4 + (float)c3 * c3 + (float)c2 * c2 +
                       (float)c1 * c1 + (float)c0 * c0;
            float cntf = 0.5f * ((float)NN * NN - sq);
            g_rowScale[row] = 0.6931471805599453f /
                              (idcg * (cntf + EPS)) / (float)BB;
        }
    }
}

// ---------------- Kernel 2: valid pairs, warp-uniform bounds -------------------
// grid (8, 64), 256 threads. Thread owns sorted positions t and 511-t.
// lo is non-decreasing in position -> warp-uniform lo from lane 0 / lane 31;
// extra pairs (lane lo > warp lo) clamp to exactly 0 via fmaxf. All lanes read
// the same sj[j] -> broadcast LDS, clean unroll. Two accs break the FFMA chain.
__global__ __launch_bounds__(256, 8)
void lr_pairs(float* __restrict__ out) {
    __shared__ float4 sj[NN];
    __shared__ float  ws[8];
    const int row = blockIdx.y;
    const int c   = blockIdx.x;      // 0..7
    const int t   = threadIdx.x;

    const float4* items = g_items + row * NN;
    sj[t]       = items[t];
    sj[t + 256] = items[t + 256];
    __syncthreads();

    float acc0 = 0.0f, acc1 = 0.0f;

    {   // item A: position t (warp-uniform lo from lane 0)
        float4 mi = sj[t];
        int lou = __shfl_sync(0xffffffffu, __float_as_int(mi.w), 0);
        int len = NN - lou;
        int j0 = lou + ((c * len) >> 3);
        int j1 = lou + (((c + 1) * len) >> 3);
        float gi = mi.x, di = mi.y;
        float Ei = __fdividef(1.0f, mi.z);              // exp(-s_i)
        #pragma unroll 8
        for (int j = j0; j < j1; ++j) {
            float4 mj = sj[j];
            float w = fmaxf(gi - mj.x, 0.0f) * fabsf(di - mj.y);
            float u = Ei * mj.z;                        // exp(s_j - s_i)
            float lg = __log2f(1.0f + u);               // ln2 folded in rowScale
            if (j & 1) acc1 = fmaf(w, lg, acc1);
            else       acc0 = fmaf(w, lg, acc0);
        }
    }
    {   // item B: position 511-t (warp-uniform lo from lane 31)
        float4 mi = sj[NN - 1 - t];
        int lou = __shfl_sync(0xffffffffu, __float_as_int(mi.w), 31);
        int len = NN - lou;
        int j0 = lou + ((c * len) >> 3);
        int j1 = lou + (((c + 1) * len) >> 3);
        float gi = mi.x, di = mi.y;
        float Ei = __fdividef(1.0f, mi.z);
        #pragma unroll 8
        for (int j = j0; j < j1; ++j) {
            float4 mj = sj[j];
            float w = fmaxf(gi - mj.x, 0.0f) * fabsf(di - mj.y);
            float u = Ei * mj.z;
            float lg = __log2f(1.0f + u);
            if (j & 1) acc1 = fmaf(w, lg, acc1);
            else       acc0 = fmaf(w, lg, acc0);
        }
    }
    float acc = acc0 + acc1;

    // block reduce (8 warps)
    #pragma unroll
    for (int o = 16; o > 0; o >>= 1) acc += __shfl_down_sync(0xffffffffu, acc, o);
    if ((t & 31) == 0) ws[t >> 5] = acc;
    __syncthreads();
    if (t < 32) {
        float bs = (t < 8) ? ws[t] : 0.0f;
        #pragma unroll
        for (int o = 4; o > 0; o >>= 1) bs += __shfl_down_sync(0xffffffffu, bs, o);
        if (t == 0) {
            atomicAdd(&g_accum, bs * g_rowScale[row]);
            __threadfence();
            unsigned n = atomicAdd(&g_count, 1u);
            if (n == 8u * BB - 1u) {             // last block finalizes + resets
                out[0] = atomicAdd(&g_accum, 0.0f);
                g_accum = 0.0f;
                g_count = 0u;
                for (int k = 0; k < BB * 5; ++k) g_slot[k] = 0u;
            }
        }
    }
}

extern "C" void kernel_launch(void* const* d_in, const int* in_sizes, int n_in,
                              void* d_out, int out_size) {
    const float* scores    = (const float*)d_in[0];
    const float* relevance = (const float*)d_in[1];
    float* out = (float*)d_out;

    lr_prep<<<dim3(16, BB), 256>>>(scores, relevance);
    lr_pairs<<<dim3(8, BB), 256>>>(out);
}

// round 8
// speedup vs baseline: 1.1109x; 1.1109x over previous
#include <cuda_runtime.h>

#define BB 64
#define NN 512
#define EPS 1e-10f

// Scratch (allocation-free rule: __device__ globals)
// Items at RELEVANCE-SORTED positions: {gain, disc, exp(score), lo_as_int}
// lo = first sorted position with strictly lower relevance.
__device__ float4   g_items[BB * NN];
__device__ float    g_rowScale[BB];     // ln2 / (idcg * (cnt+eps)) / B
__device__ float    g_accum = 0.0f;
__device__ unsigned g_count = 0u;

// ---------------- Kernel 1: ranks + sorted placement + row constants -----------
// grid (8, 64), 256 threads. Block q owns items [q*64, q*64+64).
// 4 threads/item, j = 4*jj + part (adjacent float2 addrs -> conflict-free).
// Tie-break (j < i) via loop split. Histogram via warp ballots (no serialized
// atomics). Deterministic within-bucket placement via same-rel scan.
__global__ __launch_bounds__(256, 8)
void lr_prep(const float* __restrict__ scores,
             const float* __restrict__ relevance) {
    const int q   = blockIdx.x;
    const int row = blockIdx.y;
    const int t   = threadIdx.x;

    __shared__ float2 sv[NN];           // {score, rel}
    __shared__ int    counts[5];
    __shared__ float  wred[8];

    if (t < 5) counts[t] = 0;
    float s0 = scores[row * NN + t],    s1 = scores[row * NN + t + 256];
    float r0 = relevance[row * NN + t], r1 = relevance[row * NN + t + 256];
    sv[t]       = make_float2(s0, r0);
    sv[t + 256] = make_float2(s1, r1);
    __syncthreads();

    // histogram via ballots: ~20 instr/warp instead of 64 serialized atomics
    {
        int r0i = (int)r0, r1i = (int)r1;
        int h1 = __popc(__ballot_sync(~0u, r0i == 1)) + __popc(__ballot_sync(~0u, r1i == 1));
        int h2 = __popc(__ballot_sync(~0u, r0i == 2)) + __popc(__ballot_sync(~0u, r1i == 2));
        int h3 = __popc(__ballot_sync(~0u, r0i == 3)) + __popc(__ballot_sync(~0u, r1i == 3));
        int h4 = __popc(__ballot_sync(~0u, r0i == 4)) + __popc(__ballot_sync(~0u, r1i == 4));
        if ((t & 31) == 0) {
            atomicAdd(&counts[1], h1); atomicAdd(&counts[2], h2);
            atomicAdd(&counts[3], h3); atomicAdd(&counts[4], h4);
        }
    }

    // scan: score-rank + same-rel-lower-index count
    const int   i    = q * 64 + (t >> 2);
    const int   part = t & 3;
    const float2 self = sv[i];
    const float si  = self.x;
    const float rif = self.y;
    const int   thr = (i - part + 3) >> 2;    // #jj with 4jj+part < i

    int rk = 0, same = 0, jj = 0;
    #pragma unroll 8
    for (; jj < thr; ++jj) {                  // region j < i
        float2 v = sv[4 * jj + part];
        rk   += (v.x >= si);                  // (x>si) || (x==si && j<i)
        same += (v.y == rif);
    }
    #pragma unroll 8
    for (; jj < 128; ++jj)                    // region j >= i (incl. self)
        rk += (sv[4 * jj + part].x > si);

    int pk = rk | (same << 16);               // pack; no cross-field carry
    pk += __shfl_down_sync(0xffffffffu, pk, 2, 4);
    pk += __shfl_down_sync(0xffffffffu, pk, 1, 4);

    __syncthreads();                          // histogram complete
    const int c4 = counts[4], c3 = counts[3], c2 = counts[2], c1 = counts[1];

    if (part == 0) {
        int rkT   = pk & 0xffff;
        int sameT = pk >> 16;
        int r = (int)rif;
        int base = (r == 4) ? 0
                 : (r == 3) ? c4
                 : (r == 2) ? c4 + c3
                 : (r == 1) ? c4 + c3 + c2
                            : c4 + c3 + c2 + c1;
        int cr = (r == 4) ? c4 : (r == 3) ? c3 : (r == 2) ? c2
               : (r == 1) ? c1 : (NN - (c4 + c3 + c2 + c1));
        float g = (float)((1 << r) - 1);
        float d = __fdividef(1.0f, __log2f((float)(rkT + 3)));  // rank = rkT+1
        g_items[row * NN + base + sameT] =
            make_float4(g, d, __expf(si), __int_as_float(base + cr));
    }

    // Row constants (q==0 only; block-uniform branch)
    if (q == 0) {
        int b4 = c4, b3 = b4 + c3, b2 = b3 + c2, b1 = b2 + c1;
        float v = 0.0f;
        #pragma unroll
        for (int h = 0; h < 2; ++h) {
            int p = t + h * 256;
            float gl = p < b4 ? 15.f : p < b3 ? 7.f : p < b2 ? 3.f : p < b1 ? 1.f : 0.f;
            v += __fdividef(gl, __log2f((float)(p + 2)));
        }
        #pragma unroll
        for (int o = 16; o > 0; o >>= 1) v += __shfl_down_sync(0xffffffffu, v, o);
        if ((t & 31) == 0) wred[t >> 5] = v;
        __syncthreads();
        if (t == 0) {
            float idcg = fmaxf(wred[0] + wred[1] + wred[2] + wred[3] +
                               wred[4] + wred[5] + wred[6] + wred[7], EPS);
            int c0 = NN - (c4 + c3 + c2 + c1);
            float sq = (float)c4 * c4 + (float)c3 * c3 + (float)c2 * c2 +
                       (float)c1 * c1 + (float)c0 * c0;
            float cntf = 0.5f * ((float)NN * NN - sq);
            g_rowScale[row] = 0.6931471805599453f /
                              (idcg * (cntf + EPS)) / (float)BB;
        }
    }
}

// ---------------- Kernel 2: valid pairs, warp-uniform + 2-way unrolled ---------
// grid (8, 64), 256 threads. Thread owns sorted positions t and 511-t.
// lo non-decreasing in position -> warp lo from lane 0 (item A) / lane 31 (B);
// extra pairs clamp to exactly 0 via fmaxf. Uniform j -> broadcast LDS.128.
__global__ __launch_bounds__(256, 8)
void lr_pairs(float* __restrict__ out) {
    __shared__ float4 sj[NN];
    __shared__ float  ws[8];
    const int row = blockIdx.y;
    const int c   = blockIdx.x;      // 0..7
    const int t   = threadIdx.x;

    const float4* items = g_items + row * NN;
    sj[t]       = items[t];
    sj[t + 256] = items[t + 256];
    __syncthreads();

    float acc0 = 0.0f, acc1 = 0.0f;

    {   // item A: position t (warp-uniform lo from lane 0)
        float4 mi = sj[t];
        int lou = __shfl_sync(0xffffffffu, __float_as_int(mi.w), 0);
        int len = NN - lou;
        int j0 = lou + ((c * len) >> 3);
        int j1 = lou + (((c + 1) * len) >> 3);
        float gi = mi.x, di = mi.y;
        float Ei = __fdividef(1.0f, mi.z);               // exp(-s_i)
        int j = j0;
        #pragma unroll 4
        for (; j + 1 < j1; j += 2) {
            float4 ma = sj[j], mb = sj[j + 1];
            float wa = fmaxf(gi - ma.x, 0.0f) * fabsf(di - ma.y);
            float wb = fmaxf(gi - mb.x, 0.0f) * fabsf(di - mb.y);
            acc0 = fmaf(wa, __log2f(fmaf(Ei, ma.z, 1.0f)), acc0);
            acc1 = fmaf(wb, __log2f(fmaf(Ei, mb.z, 1.0f)), acc1);
        }
        if (j < j1) {
            float4 ma = sj[j];
            float wa = fmaxf(gi - ma.x, 0.0f) * fabsf(di - ma.y);
            acc0 = fmaf(wa, __log2f(fmaf(Ei, ma.z, 1.0f)), acc0);
        }
    }
    {   // item B: position 511-t (warp-uniform lo from lane 31)
        float4 mi = sj[NN - 1 - t];
        int lou = __shfl_sync(0xffffffffu, __float_as_int(mi.w), 31);
        int len = NN - lou;
        int j0 = lou + ((c * len) >> 3);
        int j1 = lou + (((c + 1) * len) >> 3);
        float gi = mi.x, di = mi.y;
        float Ei = __fdividef(1.0f, mi.z);
        int j = j0;
        #pragma unroll 4
        for (; j + 1 < j1; j += 2) {
            float4 ma = sj[j], mb = sj[j + 1];
            float wa = fmaxf(gi - ma.x, 0.0f) * fabsf(di - ma.y);
            float wb = fmaxf(gi - mb.x, 0.0f) * fabsf(di - mb.y);
            acc0 = fmaf(wa, __log2f(fmaf(Ei, ma.z, 1.0f)), acc0);
            acc1 = fmaf(wb, __log2f(fmaf(Ei, mb.z, 1.0f)), acc1);
        }
        if (j < j1) {
            float4 ma = sj[j];
            float wa = fmaxf(gi - ma.x, 0.0f) * fabsf(di - ma.y);
            acc0 = fmaf(wa, __log2f(fmaf(Ei, ma.z, 1.0f)), acc0);
        }
    }
    float acc = acc0 + acc1;

    // block reduce (8 warps)
    #pragma unroll
    for (int o = 16; o > 0; o >>= 1) acc += __shfl_down_sync(0xffffffffu, acc, o);
    if ((t & 31) == 0) ws[t >> 5] = acc;
    __syncthreads();
    if (t < 32) {
        float bs = (t < 8) ? ws[t] : 0.0f;
        #pragma unroll
        for (int o = 4; o > 0; o >>= 1) bs += __shfl_down_sync(0xffffffffu, bs, o);
        if (t == 0) {
            atomicAdd(&g_accum, bs * g_rowScale[row]);
            __threadfence();
            unsigned n = atomicAdd(&g_count, 1u);
            if (n == 8u * BB - 1u) {             // last block finalizes + resets
                out[0] = atomicAdd(&g_accum, 0.0f);
                g_accum = 0.0f;
                g_count = 0u;
            }
        }
    }
}

extern "C" void kernel_launch(void* const* d_in, const int* in_sizes, int n_in,
                              void* d_out, int out_size) {
    const float* scores    = (const float*)d_in[0];
    const float* relevance = (const float*)d_in[1];
    float* out = (float*)d_out;

    lr_prep<<<dim3(8, BB), 256>>>(scores, relevance);
    lr_pairs<<<dim3(8, BB), 256>>>(out);
}